// round 9
// baseline (speedup 1.0000x reference)
#include <cuda_runtime.h>
#include <cstdint>

#define S_LEN 256
#define BATCH 64
#define HID   1024
#define G4    4096
#define RGRID 128

// ---------------- device scratch (no runtime allocation allowed) ------------
__device__ float    g_xz[(size_t)S_LEN * G4 * BATCH];  // 256 MB, layout [s][n][b]
__device__ unsigned g_hT[2][HID*BATCH];                // h ping-pong, tf32 bits, frag-packed
__device__ unsigned g_bar;                             // monotonic grid barrier

// ---------------- helpers ----------------------------------------------------
__device__ __forceinline__ unsigned f2tf(float x){
  unsigned u; asm("cvt.rna.tf32.f32 %0, %1;" : "=r"(u) : "f"(x)); return u;
}
__device__ __forceinline__ void mma8(float* d, const unsigned* a, unsigned b0, unsigned b1){
  asm volatile("mma.sync.aligned.m16n8k8.row.col.f32.tf32.tf32.f32 "
      "{%0,%1,%2,%3},{%4,%5,%6,%7},{%8,%9},{%0,%1,%2,%3};"
      : "+f"(d[0]),"+f"(d[1]),"+f"(d[2]),"+f"(d[3])
      : "r"(a[0]),"r"(a[1]),"r"(a[2]),"r"(a[3]),"r"(b0),"r"(b1));
}
__device__ __forceinline__ unsigned ld_acq(const unsigned* p){
  unsigned v; asm volatile("ld.acquire.gpu.global.u32 %0, [%1];" : "=r"(v) : "l"(p)); return v;
}
__device__ __forceinline__ uint4 ldcg4(const uint4* p){
  uint4 v;
  asm volatile("ld.global.cg.v4.u32 {%0,%1,%2,%3}, [%4];"
    : "=r"(v.x),"=r"(v.y),"=r"(v.z),"=r"(v.w) : "l"(p));
  return v;
}
// frag-packed word index for h element B[k=j][n=b]:
// uint4 at (k8, p, lane) holds {B[8k8+tig][16p+gid], B[8k8+tig+4][16p+gid],
//                               B[8k8+tig][16p+8+gid], B[8k8+tig+4][16p+8+gid]}
__device__ __forceinline__ unsigned hW(unsigned j, unsigned b){
  return (j>>3)*512u + (b>>4)*128u + ((b&7u)*4u + (j&3u))*4u
       + ((j>>2)&1u) + 2u*((b>>3)&1u);
}

// ---------------- phase 1: xz = x @ Wx^T + b  (tf32 mma GEMM) + fused init ---
// BM=128, BN=64, BK=32, 8 warps (4m x 2n), warp tile 32x32.
// Register software pipeline: K-block kb+32 prefetched to regs during the
// MMAs of kb, so the L2/DRAM latency hides under tensor work.
__global__ void __launch_bounds__(256,2) gemm_xz_kernel(
    const float* __restrict__ x, const float* __restrict__ h0,
    const float* __restrict__ Wf, const float* __restrict__ Wi,
    const float* __restrict__ Wg, const float* __restrict__ Wo,
    const float* __restrict__ bfp, const float* __restrict__ bip,
    const float* __restrict__ bgp, const float* __restrict__ bop)
{
  // fused init: block (0,0) resets barrier and writes h0 (tf32, frag-packed)
  if (blockIdx.x==0 && blockIdx.y==0) {
    if (threadIdx.x==0) g_bar = 0u;
    for (int i = threadIdx.x; i < BATCH*HID; i += 256) {
      int b = i >> 10, j = i & 1023;
      g_hT[0][hW(j, b)] = f2tf(h0[i]);
    }
  }

  __shared__ unsigned a_s[128][36];   // pad 36 -> conflict-free fragment loads
  __shared__ unsigned b_s[64][36];
  const int m0 = blockIdx.y*128, n0 = blockIdx.x*64;
  const int tid = threadIdx.x, wid = tid>>5, lane = tid&31;
  const int wm = wid&3, wn = wid>>2, gid = lane>>2, tig = lane&3;
  // this CTA's 64 N-columns lie inside a single gate block (64 | 1024)
  const int gate = n0 >> 10;
  const float* Wp = (gate==0)?Wf:(gate==1)?Wi:(gate==2)?Wg:Wo;
  const float* bp = (gate==0)?bfp:(gate==1)?bip:(gate==2)?bgp:bop;

  float acc[2][4][4];
  #pragma unroll
  for (int u=0;u<2;u++)
    #pragma unroll
    for (int v=0;v<4;v++)
      #pragma unroll
      for (int w=0;w<4;w++) acc[u][v][w]=0.f;

  const int r = tid>>3, c4 = (tid&7)*4;
  const int jb0 = (n0 + r)      & 1023;
  const int jb1 = (n0 + r + 32) & 1023;

  // prologue: prefetch kb=0 into registers
  float4 ra[4], rb[2];
  #pragma unroll
  for (int i=0;i<4;i++)
    ra[i] = *reinterpret_cast<const float4*>(&x[(size_t)(m0 + r + i*32)*HID + c4]);
  rb[0] = *reinterpret_cast<const float4*>(&Wp[(size_t)jb0*2048 + c4]);
  rb[1] = *reinterpret_cast<const float4*>(&Wp[(size_t)jb1*2048 + c4]);

  for (int kb=0; kb<HID; kb+=32) {
    // store current prefetch to smem (cvt.rna to tf32 — same numerics as before)
    #pragma unroll
    for (int i=0;i<4;i++){
      int rr = r + i*32;
      a_s[rr][c4]=f2tf(ra[i].x); a_s[rr][c4+1]=f2tf(ra[i].y);
      a_s[rr][c4+2]=f2tf(ra[i].z); a_s[rr][c4+3]=f2tf(ra[i].w);
    }
    {
      b_s[r][c4]   =f2tf(rb[0].x); b_s[r][c4+1]   =f2tf(rb[0].y);
      b_s[r][c4+2] =f2tf(rb[0].z); b_s[r][c4+3]   =f2tf(rb[0].w);
      b_s[r+32][c4]  =f2tf(rb[1].x); b_s[r+32][c4+1]=f2tf(rb[1].y);
      b_s[r+32][c4+2]=f2tf(rb[1].z); b_s[r+32][c4+3]=f2tf(rb[1].w);
    }
    __syncthreads();

    // prefetch next K-block (overlaps with the MMA block below)
    if (kb+32 < HID){
      #pragma unroll
      for (int i=0;i<4;i++)
        ra[i] = *reinterpret_cast<const float4*>(&x[(size_t)(m0 + r + i*32)*HID + kb+32 + c4]);
      rb[0] = *reinterpret_cast<const float4*>(&Wp[(size_t)jb0*2048 + kb+32 + c4]);
      rb[1] = *reinterpret_cast<const float4*>(&Wp[(size_t)jb1*2048 + kb+32 + c4]);
    }

    #pragma unroll
    for (int k8=0;k8<4;k8++){
      unsigned af[2][4], bfr[4][2];
      #pragma unroll
      for (int mt=0;mt<2;mt++){
        int row = wm*32 + mt*16;
        af[mt][0]=a_s[row+gid  ][k8*8+tig];
        af[mt][1]=a_s[row+gid+8][k8*8+tig];
        af[mt][2]=a_s[row+gid  ][k8*8+tig+4];
        af[mt][3]=a_s[row+gid+8][k8*8+tig+4];
      }
      #pragma unroll
      for (int nt=0;nt<4;nt++){
        int col = wn*32 + nt*8 + gid;
        bfr[nt][0]=b_s[col][k8*8+tig];
        bfr[nt][1]=b_s[col][k8*8+tig+4];
      }
      #pragma unroll
      for (int mt=0;mt<2;mt++)
        #pragma unroll
        for (int nt=0;nt<4;nt++)
          mma8(acc[mt][nt], af[mt], bfr[nt][0], bfr[nt][1]);
    }
    __syncthreads();
  }
  // epilogue: add bias, store into [s][n][b] layout
  #pragma unroll
  for (int mt=0;mt<2;mt++){
    #pragma unroll
    for (int nt=0;nt<4;nt++){
      int row0 = m0 + wm*32 + mt*16 + gid;
      int col  = n0 + wn*32 + nt*8 + tig*2;
      int j = col & 1023;
      float b0v = bp[j], b1v = bp[j+1];
      int s0 = row0>>6,     bb0 = row0&63;
      int s1 = (row0+8)>>6, bb1 = (row0+8)&63;
      size_t base0 = (size_t)s0*((size_t)G4*BATCH) + (size_t)col*BATCH;
      size_t base1 = (size_t)s1*((size_t)G4*BATCH) + (size_t)col*BATCH;
      g_xz[base0 + bb0]         = acc[mt][nt][0] + b0v;
      g_xz[base0 + BATCH + bb0] = acc[mt][nt][1] + b1v;
      g_xz[base1 + bb1]         = acc[mt][nt][2] + b0v;
      g_xz[base1 + BATCH + bb1] = acc[mt][nt][3] + b1v;
    }
  }
}

// ---------------- phase 2 smem layout (byte offsets) -------------------------
#define OFF_WHV   0          // 8192 uint4: A-frags, idx (k8*2+mt)*32+lane (131072 B)
#define OFF_RED   131072     // 8 kw x (2 nh x 32 m x 32 b) f32, XOR-swizzled (65536 B)
#define OFF_ZBUF  196608     // 32 x 65 f32 (8320 B)
#define OFF_CS    204928     // 64 x 8 f32 (2048 B)
#define SMEM2_BYTES 206976

// ---------------- phase 2: persistent recurrent kernel -----------------------
// 128 CTAs (1/SM), 512 threads (16 warps). CTA c owns hidden units [8c,8c+8):
// z^T[32 gate-j][64 b]. Warp (kw = wid&7, nh = wid>>3): kw picks K-slice
// {kw,kw+8,...,kw+120}, nh picks a 32-batch half; acc[2][4][4].
// A = Wh frag-packed smem (LDS.128); B = h via L2 ld.global.cg.v4 (frag-packed),
// depth-2 register prefetch. Cross-warp reduction in smem, gates, atomic-counter
// grid barrier (R5-proven).
__global__ void __launch_bounds__(512,1) lstm_steps_kernel(
    const float* __restrict__ x, const float* __restrict__ c0,
    const float* __restrict__ Wf,const float* __restrict__ Wi,
    const float* __restrict__ Wg,const float* __restrict__ Wo,
    float* __restrict__ out)
{
  extern __shared__ char smem[];
  uint4*    whv4 = reinterpret_cast<uint4*>(smem + OFF_WHV);
  unsigned* whvw = reinterpret_cast<unsigned*>(smem + OFF_WHV);
  float*    red  = reinterpret_cast<float*>(smem + OFF_RED);
  float*    zbuf = reinterpret_cast<float*>(smem + OFF_ZBUF);   // stride 65
  float*    cs   = reinterpret_cast<float*>(smem + OFF_CS);

  const int tid = threadIdx.x, wid = tid>>5, lane = tid&31;
  const int gid = lane>>2, tig = lane&3;
  const int kw = wid & 7, nh = wid >> 3;
  const int cta = blockIdx.x, j0 = cta*8;

  // ---- prologue: pack Wh A-frags into smem (512 threads: 2 c-rows/pass) -----
  for (int cc = 0; cc < 16; cc++){
    int c = cc*2 + (tid>>8);           // local z row 0..31
    int gatec = c & 3, jl = c >> 2;
    const float* Wp = (gatec==0)?Wf:(gatec==1)?Wi:(gatec==2)?Wg:Wo;
    int kbase = (tid & 255)*4;
    float4 v = *reinterpret_cast<const float4*>(&Wp[(size_t)(j0+jl)*2048 + 1024 + kbase]);
    float vv[4] = {v.x, v.y, v.z, v.w};
    #pragma unroll
    for (int q=0;q<4;q++){
      int k = kbase + q;
      unsigned word = (unsigned)(((k>>3)*2 + (c>>4))*128
                    + ((c&7)*4 + (k&3))*4
                    + ((c>>3)&1) + 2*((k>>2)&1));
      whvw[word] = f2tf(vv[q]);
    }
  }
  {  // cs init: one element per thread (t = b*8 + jl)
    int b = tid>>3, jl = tid&7;
    cs[tid] = c0[b*HID + j0 + jl];
  }
  __syncthreads();

  const size_t HSEQ = (size_t)S_LEN*BATCH*HID;
  // sum-phase / xz coordinates
  const int sm_m  = tid>>4;                 // z row 0..31
  const int sm_nh = (tid>>3)&1;             // batch half
  const int sm_bq = tid&7;                  // float4 block in half
  const int sm_b  = sm_nh*32 + sm_bq*4;
  const int sm_gcol = (sm_m&3)*HID + j0 + (sm_m>>2);
  const int sm_rd = sm_nh*1024 + sm_m*32 + ((sm_bq ^ ((sm_m&3)<<1))<<2);
  // gate-phase coordinates
  const int gp_jl = tid & 7, gp_b = tid >> 3;
  // K-loop B indices
  const int p0 = nh*2;
  const unsigned bi0 = (unsigned)(p0*32 + lane);
  const unsigned bi1 = (unsigned)((p0+1)*32 + lane);

  // xz prefetch for step 0
  float4 px = *reinterpret_cast<const float4*>(
      &g_xz[(size_t)sm_gcol*BATCH + sm_b]);

  for (int s=0; s<S_LEN; s++){
    const uint4* hB = reinterpret_cast<const uint4*>(g_hT[s&1]);

    // ---- K loop: k8 = kw + 8g, g=0..15; depth-2 register prefetch ----------
    float acc[2][4][4];
    #pragma unroll
    for (int u=0;u<2;u++)
      #pragma unroll
      for (int v=0;v<4;v++)
        #pragma unroll
        for (int q=0;q<4;q++) acc[u][v][q]=0.f;

    uint4 bq[2][2];
    bq[0][0] = ldcg4(hB + ((unsigned)kw*128u + bi0));
    bq[0][1] = ldcg4(hB + ((unsigned)kw*128u + bi1));
    bq[1][0] = ldcg4(hB + ((unsigned)(kw+8)*128u + bi0));
    bq[1][1] = ldcg4(hB + ((unsigned)(kw+8)*128u + bi1));

    #pragma unroll
    for (int g=0; g<16; g++){
      const int k8 = kw + 8*g;
      uint4 c0v = bq[g&1][0], c1v = bq[g&1][1];
      if (g < 14){
        bq[g&1][0] = ldcg4(hB + ((unsigned)(k8+16)*128u + bi0));
        bq[g&1][1] = ldcg4(hB + ((unsigned)(k8+16)*128u + bi1));
      }
      uint4 av0 = whv4[(k8*2+0)*32 + lane];
      uint4 av1 = whv4[(k8*2+1)*32 + lane];
      mma8(acc[0][0], reinterpret_cast<unsigned*>(&av0), c0v.x, c0v.y);
      mma8(acc[0][1], reinterpret_cast<unsigned*>(&av0), c0v.z, c0v.w);
      mma8(acc[0][2], reinterpret_cast<unsigned*>(&av0), c1v.x, c1v.y);
      mma8(acc[0][3], reinterpret_cast<unsigned*>(&av0), c1v.z, c1v.w);
      mma8(acc[1][0], reinterpret_cast<unsigned*>(&av1), c0v.x, c0v.y);
      mma8(acc[1][1], reinterpret_cast<unsigned*>(&av1), c0v.z, c0v.w);
      mma8(acc[1][2], reinterpret_cast<unsigned*>(&av1), c1v.x, c1v.y);
      mma8(acc[1][3], reinterpret_cast<unsigned*>(&av1), c1v.z, c1v.w);
    }

    // ---- store partials (XOR-swizzled float2) ------------------------------
    {
      float* rp = &red[kw*2048 + nh*1024];
      #pragma unroll
      for (int mt=0;mt<2;mt++){
        #pragma unroll
        for (int j=0;j<4;j++){
          int m  = mt*16 + gid;
          int bb = j*8 + 2*tig;
          int sw = (m&3)<<3;      // same for m and m+8
          *reinterpret_cast<float2*>(&rp[m*32 + (bb ^ sw)])
              = make_float2(acc[mt][j][0], acc[mt][j][1]);
          *reinterpret_cast<float2*>(&rp[(m+8)*32 + (bb ^ sw)])
              = make_float2(acc[mt][j][2], acc[mt][j][3]);
        }
      }
    }
    __syncthreads();

    // ---- sum across 8 kw + xz ----------------------------------------------
    {
      float4 z = px;
      #pragma unroll
      for (int w8=0; w8<8; w8++){
        float4 a = *reinterpret_cast<const float4*>(&red[w8*2048 + sm_rd]);
        z.x += a.x; z.y += a.y; z.z += a.z; z.w += a.w;
      }
      zbuf[sm_m*65 + sm_b + 0] = z.x;
      zbuf[sm_m*65 + sm_b + 1] = z.y;
      zbuf[sm_m*65 + sm_b + 2] = z.z;
      zbuf[sm_m*65 + sm_b + 3] = z.w;
    }
    __syncthreads();

    // xz prefetch for next step — before gates + barrier so its latency hides
    if (s < S_LEN-1){
      px = *reinterpret_cast<const float4*>(
          &g_xz[(size_t)(s+1)*((size_t)G4*BATCH) + (size_t)sm_gcol*BATCH + sm_b]);
    }

    // ---- gates + state update + outputs ------------------------------------
    unsigned* hwv = g_hT[(s+1)&1];
    {
      int jl = gp_jl, b = gp_b;
      int cbase = jl*4;
      float zf = zbuf[(cbase+0)*65 + b];
      float zi = zbuf[(cbase+1)*65 + b];
      float zg = zbuf[(cbase+2)*65 + b];
      float zo = zbuf[(cbase+3)*65 + b];
      float fg = 1.f/(1.f+__expf(-zf));
      float ig = 1.f/(1.f+__expf(-zi));
      float gg = tanhf(zg);
      float og = 1.f/(1.f+__expf(-zo));
      float cc = fg*cs[tid] + ig*gg;
      float hh = og*tanhf(cc);
      cs[tid] = cc;
      int j = j0 + jl;
      size_t xi = ((size_t)(s*BATCH + b))*HID + j;
      out[xi] = x[xi] + hh;
      __stcg(&hwv[hW((unsigned)j, (unsigned)b)], f2tf(hh));
      if (s == S_LEN-1){
        out[HSEQ + (size_t)b*HID + j]                     = hh;   // h_f
        out[HSEQ + (size_t)BATCH*HID + (size_t)b*HID + j] = cc;   // c_f
      }
    }

    // ---- monotonic atomic grid barrier (R5-proven; skip after last step) ----
    if (s < S_LEN-1){
      __syncthreads();
      if (tid == 0){
        __threadfence();
        atomicAdd(&g_bar, 1u);
        unsigned target = (unsigned)RGRID * (unsigned)(s+1);
        while (ld_acq(&g_bar) < target) { }
      }
      __syncthreads();
    }
  }
}

// ---------------- launch ------------------------------------------------------
extern "C" void kernel_launch(void* const* d_in, const int* in_sizes, int n_in,
                              void* d_out, int out_size) {
  const float* x   = (const float*)d_in[0];
  const float* h0  = (const float*)d_in[1];
  const float* c0  = (const float*)d_in[2];
  const float* Wf  = (const float*)d_in[3];
  const float* bf_ = (const float*)d_in[4];
  const float* Wi  = (const float*)d_in[5];
  const float* bi_ = (const float*)d_in[6];
  const float* Wg  = (const float*)d_in[7];
  const float* bg_ = (const float*)d_in[8];
  const float* Wo  = (const float*)d_in[9];
  const float* bo_ = (const float*)d_in[10];
  float* out = (float*)d_out;

  cudaFuncSetAttribute(lstm_steps_kernel,
                       cudaFuncAttributeMaxDynamicSharedMemorySize, SMEM2_BYTES);

  gemm_xz_kernel<<<dim3(64,128),256>>>(x, h0, Wf,Wi,Wg,Wo, bf_,bi_,bg_,bo_);
  lstm_steps_kernel<<<RGRID,512,SMEM2_BYTES>>>(x, c0, Wf,Wi,Wg,Wo, out);
}

// round 10
// speedup vs baseline: 1.1944x; 1.1944x over previous
#include <cuda_runtime.h>
#include <cstdint>

#define S_LEN 256
#define BATCH 64
#define HID   1024
#define G4    4096
#define RGRID 128

// ---------------- device scratch (no runtime allocation allowed) ------------
__device__ float    g_xz[(size_t)S_LEN * G4 * BATCH];  // 256 MB, layout [s][n][b]
__device__ unsigned g_hT[2][HID*BATCH];                // h ping-pong, tf32 bits, frag-packed
__device__ unsigned g_bar;                             // monotonic grid barrier

// ---------------- helpers ----------------------------------------------------
__device__ __forceinline__ unsigned f2tf(float x){
  unsigned u; asm("cvt.rna.tf32.f32 %0, %1;" : "=r"(u) : "f"(x)); return u;
}
__device__ __forceinline__ float tanh_ap(float x){
  float y; asm("tanh.approx.f32 %0, %1;" : "=f"(y) : "f"(x)); return y;
}
__device__ __forceinline__ void mma8(float* d, const unsigned* a, unsigned b0, unsigned b1){
  asm volatile("mma.sync.aligned.m16n8k8.row.col.f32.tf32.tf32.f32 "
      "{%0,%1,%2,%3},{%4,%5,%6,%7},{%8,%9},{%0,%1,%2,%3};"
      : "+f"(d[0]),"+f"(d[1]),"+f"(d[2]),"+f"(d[3])
      : "r"(a[0]),"r"(a[1]),"r"(a[2]),"r"(a[3]),"r"(b0),"r"(b1));
}
__device__ __forceinline__ unsigned ld_acq(const unsigned* p){
  unsigned v; asm volatile("ld.acquire.gpu.global.u32 %0, [%1];" : "=r"(v) : "l"(p)); return v;
}
__device__ __forceinline__ uint4 ldcg4(const uint4* p){
  uint4 v;
  asm volatile("ld.global.cg.v4.u32 {%0,%1,%2,%3}, [%4];"
    : "=r"(v.x),"=r"(v.y),"=r"(v.z),"=r"(v.w) : "l"(p));
  return v;
}
// frag-packed word index for h element B[k=j][n=b]:
// uint4 at (k8, p, lane) holds {B[8k8+tig][16p+gid], B[8k8+tig+4][16p+gid],
//                               B[8k8+tig][16p+8+gid], B[8k8+tig+4][16p+8+gid]}
__device__ __forceinline__ unsigned hW(unsigned j, unsigned b){
  return (j>>3)*512u + (b>>4)*128u + ((b&7u)*4u + (j&3u))*4u
       + ((j>>2)&1u) + 2u*((b>>3)&1u);
}

// ---------------- phase 1: xz = x @ Wx^T + b  (tf32 mma GEMM) + fused init ---
// R5-proven tile: BM=BN=128, BK=32, 8 warps (4m x 2n), warp tile 32x64.
__global__ void __launch_bounds__(256,2) gemm_xz_kernel(
    const float* __restrict__ x, const float* __restrict__ h0,
    const float* __restrict__ Wf, const float* __restrict__ Wi,
    const float* __restrict__ Wg, const float* __restrict__ Wo,
    const float* __restrict__ bfp, const float* __restrict__ bip,
    const float* __restrict__ bgp, const float* __restrict__ bop)
{
  // fused init: block (0,0) resets barrier and writes h0 (tf32, frag-packed)
  if (blockIdx.x==0 && blockIdx.y==0) {
    if (threadIdx.x==0) g_bar = 0u;
    for (int i = threadIdx.x; i < BATCH*HID; i += 256) {
      int b = i >> 10, j = i & 1023;
      g_hT[0][hW(j, b)] = f2tf(h0[i]);
    }
  }

  __shared__ unsigned a_s[128][36];
  __shared__ unsigned b_s[128][36];
  const int m0 = blockIdx.y*128, n0 = blockIdx.x*128;
  const int tid = threadIdx.x, wid = tid>>5, lane = tid&31;
  const int wm = wid&3, wn = wid>>2, gid = lane>>2, tig = lane&3;
  const int gate = n0 >> 10;
  const float* Wp = (gate==0)?Wf:(gate==1)?Wi:(gate==2)?Wg:Wo;
  const float* bp = (gate==0)?bfp:(gate==1)?bip:(gate==2)?bgp:bop;

  float acc[2][8][4];
  #pragma unroll
  for (int u=0;u<2;u++)
    #pragma unroll
    for (int v=0;v<8;v++)
      #pragma unroll
      for (int w=0;w<4;w++) acc[u][v][w]=0.f;

  const int r = tid>>3, c4 = (tid&7)*4;
  for (int kb=0; kb<HID; kb+=32) {
    #pragma unroll
    for (int rr=r; rr<128; rr+=32) {
      float4 v = *reinterpret_cast<const float4*>(&x[(size_t)(m0+rr)*HID + kb + c4]);
      a_s[rr][c4]=f2tf(v.x); a_s[rr][c4+1]=f2tf(v.y);
      a_s[rr][c4+2]=f2tf(v.z); a_s[rr][c4+3]=f2tf(v.w);
    }
    #pragma unroll
    for (int rr=r; rr<128; rr+=32) {
      int j = (n0 + rr) & 1023;
      float4 v = *reinterpret_cast<const float4*>(&Wp[(size_t)j*2048 + kb + c4]);
      b_s[rr][c4]=f2tf(v.x); b_s[rr][c4+1]=f2tf(v.y);
      b_s[rr][c4+2]=f2tf(v.z); b_s[rr][c4+3]=f2tf(v.w);
    }
    __syncthreads();
    #pragma unroll
    for (int k8=0;k8<4;k8++){
      unsigned af[2][4], bfr[8][2];
      #pragma unroll
      for (int mt=0;mt<2;mt++){
        int row = wm*32 + mt*16;
        af[mt][0]=a_s[row+gid  ][k8*8+tig];
        af[mt][1]=a_s[row+gid+8][k8*8+tig];
        af[mt][2]=a_s[row+gid  ][k8*8+tig+4];
        af[mt][3]=a_s[row+gid+8][k8*8+tig+4];
      }
      #pragma unroll
      for (int nt=0;nt<8;nt++){
        int col = wn*64 + nt*8 + gid;
        bfr[nt][0]=b_s[col][k8*8+tig];
        bfr[nt][1]=b_s[col][k8*8+tig+4];
      }
      #pragma unroll
      for (int mt=0;mt<2;mt++)
        #pragma unroll
        for (int nt=0;nt<8;nt++)
          mma8(acc[mt][nt], af[mt], bfr[nt][0], bfr[nt][1]);
    }
    __syncthreads();
  }
  #pragma unroll
  for (int mt=0;mt<2;mt++){
    #pragma unroll
    for (int nt=0;nt<8;nt++){
      int row0 = m0 + wm*32 + mt*16 + gid;
      int col  = n0 + wn*64 + nt*8 + tig*2;
      int j = col & 1023;
      float b0v = bp[j], b1v = bp[j+1];
      int s0 = row0>>6,     bb0 = row0&63;
      int s1 = (row0+8)>>6, bb1 = (row0+8)&63;
      size_t base0 = (size_t)s0*((size_t)G4*BATCH) + (size_t)col*BATCH;
      size_t base1 = (size_t)s1*((size_t)G4*BATCH) + (size_t)col*BATCH;
      g_xz[base0 + bb0]         = acc[mt][nt][0] + b0v;
      g_xz[base0 + BATCH + bb0] = acc[mt][nt][1] + b1v;
      g_xz[base1 + bb1]         = acc[mt][nt][2] + b0v;
      g_xz[base1 + BATCH + bb1] = acc[mt][nt][3] + b1v;
    }
  }
}

// ---------------- phase 2 smem layout (byte offsets) -------------------------
#define OFF_WHV   0          // 8192 uint4: A-frags, idx (k8*2+mt)*32+lane (131072 B)
#define OFF_RED   131072     // 8 kw x (2 nh x 32 m x 32 b) f32, XOR-swizzled (65536 B)
#define OFF_ZBUF  196608     // 32 x 65 f32 (8320 B)
#define OFF_CS    204928     // 64 x 8 f32 (2048 B)
#define SMEM2_BYTES 206976

// ---------------- phase 2: persistent recurrent kernel -----------------------
// 128 CTAs (1/SM), 512 threads (16 warps). CTA c owns hidden units [8c,8c+8):
// z^T[32 gate-j][64 b]. Warp (kw = wid&7, nh = wid>>3): kw picks K-slice
// {kw,kw+8,...,kw+120}, nh picks a 32-batch half; acc[2][4][4].
// A = Wh frag-packed smem (LDS.128); B = h via L2 ld.global.cg.v4 (frag-packed),
// depth-2 register prefetch. Cross-warp reduction in smem; gates via
// tanh.approx (1 MUFU each, sigmoid = 0.5*tanh(x/2)+0.5); out-writes overlap
// the barrier-poll window; atomic-counter grid barrier (R5-proven).
__global__ void __launch_bounds__(512,1) lstm_steps_kernel(
    const float* __restrict__ x, const float* __restrict__ c0,
    const float* __restrict__ Wf,const float* __restrict__ Wi,
    const float* __restrict__ Wg,const float* __restrict__ Wo,
    float* __restrict__ out)
{
  extern __shared__ char smem[];
  uint4*    whv4 = reinterpret_cast<uint4*>(smem + OFF_WHV);
  unsigned* whvw = reinterpret_cast<unsigned*>(smem + OFF_WHV);
  float*    red  = reinterpret_cast<float*>(smem + OFF_RED);
  float*    zbuf = reinterpret_cast<float*>(smem + OFF_ZBUF);   // stride 65
  float*    cs   = reinterpret_cast<float*>(smem + OFF_CS);

  const int tid = threadIdx.x, wid = tid>>5, lane = tid&31;
  const int gid = lane>>2, tig = lane&3;
  const int kw = wid & 7, nh = wid >> 3;
  const int cta = blockIdx.x, j0 = cta*8;

  // ---- prologue: pack Wh A-frags into smem (512 threads: 2 c-rows/pass) -----
  for (int cc = 0; cc < 16; cc++){
    int c = cc*2 + (tid>>8);           // local z row 0..31
    int gatec = c & 3, jl = c >> 2;
    const float* Wp = (gatec==0)?Wf:(gatec==1)?Wi:(gatec==2)?Wg:Wo;
    int kbase = (tid & 255)*4;
    float4 v = *reinterpret_cast<const float4*>(&Wp[(size_t)(j0+jl)*2048 + 1024 + kbase]);
    float vv[4] = {v.x, v.y, v.z, v.w};
    #pragma unroll
    for (int q=0;q<4;q++){
      int k = kbase + q;
      unsigned word = (unsigned)(((k>>3)*2 + (c>>4))*128
                    + ((c&7)*4 + (k&3))*4
                    + ((c>>3)&1) + 2*((k>>2)&1));
      whvw[word] = f2tf(vv[q]);
    }
  }
  {  // cs init: one element per thread (t = b*8 + jl)
    int b = tid>>3, jl = tid&7;
    cs[tid] = c0[b*HID + j0 + jl];
  }
  __syncthreads();

  const size_t HSEQ = (size_t)S_LEN*BATCH*HID;
  // sum-phase / xz coordinates
  const int sm_m  = tid>>4;                 // z row 0..31
  const int sm_nh = (tid>>3)&1;             // batch half
  const int sm_bq = tid&7;                  // float4 block in half
  const int sm_b  = sm_nh*32 + sm_bq*4;
  const int sm_gcol = (sm_m&3)*HID + j0 + (sm_m>>2);
  const int sm_rd = sm_nh*1024 + sm_m*32 + ((sm_bq ^ ((sm_m&3)<<1))<<2);
  // gate-phase coordinates
  const int gp_jl = tid & 7, gp_b = tid >> 3;
  const int gp_j  = j0 + gp_jl;
  // K-loop B indices
  const int p0 = nh*2;
  const unsigned bi0 = (unsigned)(p0*32 + lane);
  const unsigned bi1 = (unsigned)((p0+1)*32 + lane);

  // prefetches for step 0
  float4 px = *reinterpret_cast<const float4*>(
      &g_xz[(size_t)sm_gcol*BATCH + sm_b]);
  float pxv = x[(size_t)gp_b*HID + gp_j];

  for (int s=0; s<S_LEN; s++){
    const uint4* hB = reinterpret_cast<const uint4*>(g_hT[s&1]);

    // ---- K loop: k8 = kw + 8g, g=0..15; depth-2 register prefetch ----------
    float acc[2][4][4];
    #pragma unroll
    for (int u=0;u<2;u++)
      #pragma unroll
      for (int v=0;v<4;v++)
        #pragma unroll
        for (int q=0;q<4;q++) acc[u][v][q]=0.f;

    uint4 bq[2][2];
    bq[0][0] = ldcg4(hB + ((unsigned)kw*128u + bi0));
    bq[0][1] = ldcg4(hB + ((unsigned)kw*128u + bi1));
    bq[1][0] = ldcg4(hB + ((unsigned)(kw+8)*128u + bi0));
    bq[1][1] = ldcg4(hB + ((unsigned)(kw+8)*128u + bi1));

    #pragma unroll
    for (int g=0; g<16; g++){
      const int k8 = kw + 8*g;
      uint4 c0v = bq[g&1][0], c1v = bq[g&1][1];
      if (g < 14){
        bq[g&1][0] = ldcg4(hB + ((unsigned)(k8+16)*128u + bi0));
        bq[g&1][1] = ldcg4(hB + ((unsigned)(k8+16)*128u + bi1));
      }
      uint4 av0 = whv4[(k8*2+0)*32 + lane];
      uint4 av1 = whv4[(k8*2+1)*32 + lane];
      mma8(acc[0][0], reinterpret_cast<unsigned*>(&av0), c0v.x, c0v.y);
      mma8(acc[0][1], reinterpret_cast<unsigned*>(&av0), c0v.z, c0v.w);
      mma8(acc[0][2], reinterpret_cast<unsigned*>(&av0), c1v.x, c1v.y);
      mma8(acc[0][3], reinterpret_cast<unsigned*>(&av0), c1v.z, c1v.w);
      mma8(acc[1][0], reinterpret_cast<unsigned*>(&av1), c0v.x, c0v.y);
      mma8(acc[1][1], reinterpret_cast<unsigned*>(&av1), c0v.z, c0v.w);
      mma8(acc[1][2], reinterpret_cast<unsigned*>(&av1), c1v.x, c1v.y);
      mma8(acc[1][3], reinterpret_cast<unsigned*>(&av1), c1v.z, c1v.w);
    }

    // ---- store partials (XOR-swizzled float2) ------------------------------
    {
      float* rp = &red[kw*2048 + nh*1024];
      #pragma unroll
      for (int mt=0;mt<2;mt++){
        #pragma unroll
        for (int j=0;j<4;j++){
          int m  = mt*16 + gid;
          int bb = j*8 + 2*tig;
          int sw = (m&3)<<3;      // same for m and m+8
          *reinterpret_cast<float2*>(&rp[m*32 + (bb ^ sw)])
              = make_float2(acc[mt][j][0], acc[mt][j][1]);
          *reinterpret_cast<float2*>(&rp[(m+8)*32 + (bb ^ sw)])
              = make_float2(acc[mt][j][2], acc[mt][j][3]);
        }
      }
    }
    __syncthreads();

    // ---- sum across 8 kw + xz ----------------------------------------------
    {
      float4 z = px;
      #pragma unroll
      for (int w8=0; w8<8; w8++){
        float4 a = *reinterpret_cast<const float4*>(&red[w8*2048 + sm_rd]);
        z.x += a.x; z.y += a.y; z.z += a.z; z.w += a.w;
      }
      zbuf[sm_m*65 + sm_b + 0] = z.x;
      zbuf[sm_m*65 + sm_b + 1] = z.y;
      zbuf[sm_m*65 + sm_b + 2] = z.z;
      zbuf[sm_m*65 + sm_b + 3] = z.w;
    }
    __syncthreads();

    // xz prefetch for next step — before gates + barrier so its latency hides
    if (s < S_LEN-1){
      px = *reinterpret_cast<const float4*>(
          &g_xz[(size_t)(s+1)*((size_t)G4*BATCH) + (size_t)sm_gcol*BATCH + sm_b]);
    }

    // ---- gates + state update (tanh.approx: 5 MUFU/thread) -----------------
    unsigned* hwv = g_hT[(s+1)&1];
    float cc, hh;
    {
      int cbase = gp_jl*4;
      float zf = zbuf[(cbase+0)*65 + gp_b];
      float zi = zbuf[(cbase+1)*65 + gp_b];
      float zg = zbuf[(cbase+2)*65 + gp_b];
      float zo = zbuf[(cbase+3)*65 + gp_b];
      float fg = 0.5f*tanh_ap(0.5f*zf) + 0.5f;
      float ig = 0.5f*tanh_ap(0.5f*zi) + 0.5f;
      float gg = tanh_ap(zg);
      float og = 0.5f*tanh_ap(0.5f*zo) + 0.5f;
      cc = fg*cs[tid] + ig*gg;
      hh = og*tanh_ap(cc);
      cs[tid] = cc;
      __stcg(&hwv[hW((unsigned)gp_j, (unsigned)gp_b)], f2tf(hh));
    }

    // ---- barrier arrive (h published), then out-writes overlap the poll ----
    if (s < S_LEN-1){
      __syncthreads();                  // all h writes of this CTA issued
      if (tid == 0){
        __threadfence();
        atomicAdd(&g_bar, 1u);
      }
    }

    // out-writes + next-step x prefetch (off the h critical path)
    {
      size_t xi = ((size_t)(s*BATCH + gp_b))*HID + gp_j;
      out[xi] = pxv + hh;
      if (s == S_LEN-1){
        out[HSEQ + (size_t)gp_b*HID + gp_j]                     = hh;  // h_f
        out[HSEQ + (size_t)BATCH*HID + (size_t)gp_b*HID + gp_j] = cc;  // c_f
      } else {
        pxv = x[xi + (size_t)BATCH*HID];
      }
    }

    // ---- barrier wait -------------------------------------------------------
    if (s < S_LEN-1){
      if (tid == 0){
        unsigned target = (unsigned)RGRID * (unsigned)(s+1);
        while (ld_acq(&g_bar) < target) { }
      }
      __syncthreads();
    }
  }
}

// ---------------- launch ------------------------------------------------------
extern "C" void kernel_launch(void* const* d_in, const int* in_sizes, int n_in,
                              void* d_out, int out_size) {
  const float* x   = (const float*)d_in[0];
  const float* h0  = (const float*)d_in[1];
  const float* c0  = (const float*)d_in[2];
  const float* Wf  = (const float*)d_in[3];
  const float* bf_ = (const float*)d_in[4];
  const float* Wi  = (const float*)d_in[5];
  const float* bi_ = (const float*)d_in[6];
  const float* Wg  = (const float*)d_in[7];
  const float* bg_ = (const float*)d_in[8];
  const float* Wo  = (const float*)d_in[9];
  const float* bo_ = (const float*)d_in[10];
  float* out = (float*)d_out;

  cudaFuncSetAttribute(lstm_steps_kernel,
                       cudaFuncAttributeMaxDynamicSharedMemorySize, SMEM2_BYTES);

  gemm_xz_kernel<<<dim3(32,128),256>>>(x, h0, Wf,Wi,Wg,Wo, bf_,bi_,bg_,bo_);
  lstm_steps_kernel<<<RGRID,512,SMEM2_BYTES>>>(x, c0, Wf,Wi,Wg,Wo, out);
}